// round 16
// baseline (speedup 1.0000x reference)
#include <cuda_runtime.h>
#include <float.h>

#define BATCHG 64
#define NNODE 1024
#define KNN 16
#define HD 64
#define MNODES (BATCHG*NNODE)
#define NEDGES (MNODES*KNN)
#define BNEPS 1e-5f

#define KQ_SENT 0xFF800000FFFFFFFFull
#define QDEPTH 16
#define QTRIG 12

#define FMA2(d, a, b, c) \
    asm("fma.rn.f32x2 %0, %1, %2, %3;" : "=l"(d) : "l"(a), "l"(b), "l"(c))
#define ADD2(d, a, b) \
    asm("add.rn.f32x2 %0, %1, %2;" : "=l"(d) : "l"(a), "l"(b))
__device__ __forceinline__ unsigned long long pack2(float lo, float hi) {
    unsigned long long r;
    asm("mov.b64 %0, {%1, %2};" : "=l"(r) : "r"(__float_as_uint(lo)), "r"(__float_as_uint(hi)));
    return r;
}
__device__ __forceinline__ float2 unpack2(unsigned long long v) {
    unsigned int lo, hi;
    asm("mov.b64 {%0, %1}, %2;" : "=r"(lo), "=r"(hi) : "l"(v));
    return make_float2(__uint_as_float(lo), __uint_as_float(hi));
}

__device__ float g_bufA[MNODES*HD];
__device__ float g_bufB[MNODES*HD];
__device__ float g_u[MNODES*HD];
__device__ float g_v[MNODES*HD];
__device__ float g_sq[MNODES];
__device__ int   g_idx[MNODES*KNN];
__device__ float g_s1[HD], g_q1[HD], g_s2[HD], g_q2[HD], g_s3[HD], g_q3[HD];
__device__ float g_se[HD], g_qe[HD], g_sp[HD], g_qp[HD];

__global__ void zero_stats_kernel() {
    int t = threadIdx.x;
    if (t < HD) {
        g_s1[t]=0.f; g_q1[t]=0.f; g_s2[t]=0.f; g_q2[t]=0.f; g_s3[t]=0.f; g_q3[t]=0.f;
        g_se[t]=0.f; g_qe[t]=0.f; g_sp[t]=0.f; g_qp[t]=0.f;
    }
}

// Linear(64,64)+bias; prev-stage BN+ReLU fused on input; output stats. (R9 exact)
__global__ __launch_bounds__(256) void gemm_stage_kernel(
    int stage, const float* __restrict__ xin,
    const float* __restrict__ w, const float* __restrict__ bias,
    const float* __restrict__ gam, const float* __restrict__ bet)
{
    __shared__ float xs[64][64];
    __shared__ float ws[64][64];
    __shared__ float scs[64], shs[64];
    __shared__ float rs[64], rq[64];

    const float* in; float* out; float* osum; float* osq;
    const float* psum = 0; const float* psq = 0;
    if (stage == 1)      { in = xin;    out = g_bufA; osum = g_s1; osq = g_q1; }
    else if (stage == 2) { in = g_bufA; out = g_bufB; osum = g_s2; osq = g_q2; psum = g_s1; psq = g_q1; }
    else                 { in = g_bufB; out = g_bufA; osum = g_s3; osq = g_q3; psum = g_s2; psq = g_q2; }

    int tid = threadIdx.x;
    int rowBase = blockIdx.x * 64;

    if (tid < 64) {
        rs[tid] = 0.f; rq[tid] = 0.f;
        if (stage > 1) {
            float invM = 1.f / (float)MNODES;
            float m   = psum[tid] * invM;
            float var = psq[tid] * invM - m * m;
            float s   = gam[tid] * rsqrtf(var + BNEPS);
            scs[tid] = s; shs[tid] = bet[tid] - m * s;
        }
    }
    const float4* w4 = (const float4*)w;
    #pragma unroll
    for (int i = 0; i < 4; i++) {
        int q = tid + i * 256;
        float4 v = w4[q];
        int e = q << 2;
        *(float4*)&ws[e >> 6][e & 63] = v;
    }
    __syncthreads();
    const float4* in4 = (const float4*)(in + (size_t)rowBase * HD);
    #pragma unroll
    for (int i = 0; i < 4; i++) {
        int q = tid + i * 256;
        float4 v = in4[q];
        int e = q << 2; int c = e & 63;
        if (stage > 1) {
            v.x = fmaxf(fmaf(v.x, scs[c+0], shs[c+0]), 0.f);
            v.y = fmaxf(fmaf(v.y, scs[c+1], shs[c+1]), 0.f);
            v.z = fmaxf(fmaf(v.z, scs[c+2], shs[c+2]), 0.f);
            v.w = fmaxf(fmaf(v.w, scs[c+3], shs[c+3]), 0.f);
        }
        *(float4*)&xs[e >> 6][c] = v;
    }
    __syncthreads();

    int r0 = (tid >> 4) << 2, c0 = (tid & 15) << 2;
    float acc[4][4];
    #pragma unroll
    for (int i = 0; i < 4; i++)
        #pragma unroll
        for (int j = 0; j < 4; j++) acc[i][j] = 0.f;

    #pragma unroll
    for (int d = 0; d < 64; d++) {
        float x0 = xs[r0+0][d], x1 = xs[r0+1][d], x2 = xs[r0+2][d], x3 = xs[r0+3][d];
        float w0 = ws[d][c0+0], w1 = ws[d][c0+1], w2 = ws[d][c0+2], w3 = ws[d][c0+3];
        acc[0][0]=fmaf(x0,w0,acc[0][0]); acc[0][1]=fmaf(x0,w1,acc[0][1]); acc[0][2]=fmaf(x0,w2,acc[0][2]); acc[0][3]=fmaf(x0,w3,acc[0][3]);
        acc[1][0]=fmaf(x1,w0,acc[1][0]); acc[1][1]=fmaf(x1,w1,acc[1][1]); acc[1][2]=fmaf(x1,w2,acc[1][2]); acc[1][3]=fmaf(x1,w3,acc[1][3]);
        acc[2][0]=fmaf(x2,w0,acc[2][0]); acc[2][1]=fmaf(x2,w1,acc[2][1]); acc[2][2]=fmaf(x2,w2,acc[2][2]); acc[2][3]=fmaf(x2,w3,acc[2][3]);
        acc[3][0]=fmaf(x3,w0,acc[3][0]); acc[3][1]=fmaf(x3,w1,acc[3][1]); acc[3][2]=fmaf(x3,w2,acc[3][2]); acc[3][3]=fmaf(x3,w3,acc[3][3]);
    }
    float b0 = bias[c0+0], b1 = bias[c0+1], b2 = bias[c0+2], b3 = bias[c0+3];
    float lsum[4] = {0,0,0,0}, lsq[4] = {0,0,0,0};
    #pragma unroll
    for (int i = 0; i < 4; i++) {
        float4 o;
        o.x = acc[i][0] + b0; o.y = acc[i][1] + b1; o.z = acc[i][2] + b2; o.w = acc[i][3] + b3;
        *(float4*)(out + (size_t)(rowBase + r0 + i) * HD + c0) = o;
        lsum[0]+=o.x; lsq[0]=fmaf(o.x,o.x,lsq[0]);
        lsum[1]+=o.y; lsq[1]=fmaf(o.y,o.y,lsq[1]);
        lsum[2]+=o.z; lsq[2]=fmaf(o.z,o.z,lsq[2]);
        lsum[3]+=o.w; lsq[3]=fmaf(o.w,o.w,lsq[3]);
    }
    #pragma unroll
    for (int j = 0; j < 4; j++) { atomicAdd(&rs[c0+j], lsum[j]); atomicAdd(&rq[c0+j], lsq[j]); }
    __syncthreads();
    if (tid < 64) { atomicAdd(&osum[tid], rs[tid]); atomicAdd(&osq[tid], rq[tid]); }
}

// h = bn3relu(y3) -> g_bufB; u,v; g_sq row norms. (R9 exact)
__global__ __launch_bounds__(256) void layer_uv_kernel(
    const float* __restrict__ wc1, const float* __restrict__ bc1,
    const float* __restrict__ g3p, const float* __restrict__ be3p)
{
    __shared__ float xs[64][64];
    __shared__ float wa[64][64];
    __shared__ float wb[64][64];
    int tid = threadIdx.x;
    int rowBase = blockIdx.x * 64;

    const float4* w4 = (const float4*)wc1;
    #pragma unroll
    for (int i = 0; i < 4; i++) {
        int q = tid + i * 256;
        float4 va = w4[q];
        float4 vb = w4[q + 1024];
        int e = q << 2;
        float4 d4 = make_float4(va.x - vb.x, va.y - vb.y, va.z - vb.z, va.w - vb.w);
        *(float4*)&wa[e >> 6][e & 63] = d4;
        *(float4*)&wb[e >> 6][e & 63] = vb;
    }
    float invM = 1.f / (float)MNODES;
    const float4* in4 = (const float4*)(g_bufA + (size_t)rowBase * HD);
    float4* h4 = (float4*)(g_bufB + (size_t)rowBase * HD);
    float psq[4];
    #pragma unroll
    for (int i = 0; i < 4; i++) {
        int q = tid + i * 256;
        float4 v = in4[q];
        int e = q << 2; int c = e & 63;
        float* pv = &v.x;
        #pragma unroll
        for (int j = 0; j < 4; j++) {
            int cc = c + j;
            float m   = g_s3[cc] * invM;
            float var = g_q3[cc] * invM - m * m;
            float sc  = g3p[cc] * rsqrtf(var + BNEPS);
            pv[j] = fmaxf(fmaf(pv[j], sc, be3p[cc] - m * sc), 0.f);
        }
        *(float4*)&xs[e >> 6][c] = v;
        h4[q] = v;
        psq[i] = v.x*v.x + v.y*v.y + v.z*v.z + v.w*v.w;
    }
    #pragma unroll
    for (int i = 0; i < 4; i++) {
        #pragma unroll
        for (int off = 8; off; off >>= 1)
            psq[i] += __shfl_xor_sync(0xffffffffu, psq[i], off, 16);
    }
    if ((tid & 15) == 0) {
        int r = tid >> 4;
        #pragma unroll
        for (int i = 0; i < 4; i++)
            g_sq[rowBase + r + 16*i] = psq[i];
    }
    __syncthreads();

    int r0 = (tid >> 4) << 2, c0 = (tid & 15) << 2;
    float au[4][4], av[4][4];
    #pragma unroll
    for (int i = 0; i < 4; i++)
        #pragma unroll
        for (int j = 0; j < 4; j++) { au[i][j] = 0.f; av[i][j] = 0.f; }

    #pragma unroll
    for (int d = 0; d < 64; d++) {
        float x0 = xs[r0+0][d], x1 = xs[r0+1][d], x2 = xs[r0+2][d], x3 = xs[r0+3][d];
        float a0 = wa[d][c0+0], a1 = wa[d][c0+1], a2 = wa[d][c0+2], a3 = wa[d][c0+3];
        float p0 = wb[d][c0+0], p1 = wb[d][c0+1], p2 = wb[d][c0+2], p3 = wb[d][c0+3];
        au[0][0]=fmaf(x0,a0,au[0][0]); au[0][1]=fmaf(x0,a1,au[0][1]); au[0][2]=fmaf(x0,a2,au[0][2]); au[0][3]=fmaf(x0,a3,au[0][3]);
        au[1][0]=fmaf(x1,a0,au[1][0]); au[1][1]=fmaf(x1,a1,au[1][1]); au[1][2]=fmaf(x1,a2,au[1][2]); au[1][3]=fmaf(x1,a3,au[1][3]);
        au[2][0]=fmaf(x2,a0,au[2][0]); au[2][1]=fmaf(x2,a1,au[2][1]); au[2][2]=fmaf(x2,a2,au[2][2]); au[2][3]=fmaf(x2,a3,au[2][3]);
        au[3][0]=fmaf(x3,a0,au[3][0]); au[3][1]=fmaf(x3,a1,au[3][1]); au[3][2]=fmaf(x3,a2,au[3][2]); au[3][3]=fmaf(x3,a3,au[3][3]);
        av[0][0]=fmaf(x0,p0,av[0][0]); av[0][1]=fmaf(x0,p1,av[0][1]); av[0][2]=fmaf(x0,p2,av[0][2]); av[0][3]=fmaf(x0,p3,av[0][3]);
        av[1][0]=fmaf(x1,p0,av[1][0]); av[1][1]=fmaf(x1,p1,av[1][1]); av[1][2]=fmaf(x1,p2,av[1][2]); av[1][3]=fmaf(x1,p3,av[1][3]);
        av[2][0]=fmaf(x2,p0,av[2][0]); av[2][1]=fmaf(x2,p1,av[2][1]); av[2][2]=fmaf(x2,p2,av[2][2]); av[2][3]=fmaf(x2,p3,av[2][3]);
        av[3][0]=fmaf(x3,p0,av[3][0]); av[3][1]=fmaf(x3,p1,av[3][1]); av[3][2]=fmaf(x3,p2,av[3][2]); av[3][3]=fmaf(x3,p3,av[3][3]);
    }
    float bA = bc1[c0+0], bB = bc1[c0+1], bC = bc1[c0+2], bD = bc1[c0+3];
    #pragma unroll
    for (int i = 0; i < 4; i++) {
        float4 uo = make_float4(au[i][0]+bA, au[i][1]+bB, au[i][2]+bC, au[i][3]+bD);
        float4 vo = make_float4(av[i][0], av[i][1], av[i][2], av[i][3]);
        *(float4*)(g_u + (size_t)(rowBase + r0 + i) * HD + c0) = uo;
        *(float4*)(g_v + (size_t)(rowBase + r0 + i) * HD + c0) = vo;
    }
}

__device__ __forceinline__ void kq_insert(unsigned long long (&kq)[16], unsigned long long e) {
    kq[15] = e;
    #pragma unroll
    for (int p = 15; p > 0; p--) {
        bool sw = kq[p] < kq[p-1];
        unsigned long long lo = sw ? kq[p] : kq[p-1];
        unsigned long long hi = sw ? kq[p-1] : kq[p];
        kq[p-1] = lo; kq[p] = hi;
    }
}
__device__ __forceinline__ float kq_thresh(unsigned long long kq15) {
    unsigned int u = (unsigned int)(kq15 >> 32);
    u = (u & 0x80000000u) ? (u ^ 0x80000000u) : ~u;
    return __uint_as_float(u);
}

// kNN: R15 algorithm with double-buffered candidate tiles (1 barrier/iter)
// and ballots batched to every 4th candidate (QDEPTH 16, trigger >= 12).
__global__ __launch_bounds__(128, 4) void knn_kernel() {
    __shared__ float cand[2][32][68];
    __shared__ float csq[2][32];
    __shared__ unsigned long long que[QDEPTH][128];
    int b = blockIdx.y;
    int tid = threadIdx.x;
    int row = blockIdx.x * 128 + tid;
    const float* hb = g_bufB + (size_t)b * NNODE * HD;

    unsigned long long rf2[32];
    {
        const ulonglong2* rp = (const ulonglong2*)(hb + (size_t)row * HD);
        #pragma unroll
        for (int i = 0; i < 16; i++) {
            ulonglong2 t = rp[i];
            rf2[2*i] = t.x; rf2[2*i+1] = t.y;
        }
    }
    float sqr = g_sq[b * NNODE + row];

    // preload tile 0 into buffer 0
    #pragma unroll
    for (int i = 0; i < 4; i++) {
        int fi = tid + i * 128;
        int r = fi >> 4, c4 = fi & 15;
        float4 v = *(const float4*)(hb + (size_t)r * HD + (c4 << 2));
        *(float4*)&cand[0][r][c4 << 2] = v;
    }
    if (tid < 32) csq[0][tid] = g_sq[b * NNODE + tid];
    __syncthreads();

    unsigned long long kq[16];
    #pragma unroll
    for (int p = 0; p < 16; p++) kq[p] = KQ_SENT;
    float kthr = __uint_as_float(0x7F800000u);   // +inf
    int cnt = 0;

    #pragma unroll 1
    for (int t = 0; t < 32; t++) {
        int cur = t & 1;
        if (t < 31) {   // prefetch next tile into the idle buffer
            int nb = cur ^ 1;
            #pragma unroll
            for (int i = 0; i < 4; i++) {
                int fi = tid + i * 128;
                int r = fi >> 4, c4 = fi & 15;
                float4 v = *(const float4*)(hb + (size_t)(((t+1) << 5) + r) * HD + (c4 << 2));
                *(float4*)&cand[nb][r][c4 << 2] = v;
            }
            if (tid < 32) csq[nb][tid] = g_sq[b * NNODE + ((t+1) << 5) + tid];
        }

        #pragma unroll 1
        for (int m = 0; m < 32; m++) {
            unsigned long long a0 = 0ull, a1 = 0ull, a2 = 0ull, a3 = 0ull;
            const ulonglong2* cp = (const ulonglong2*)&cand[cur][m][0];
            #pragma unroll
            for (int q = 0; q < 4; q++) {
                ulonglong2 c0 = cp[4*q+0];
                ulonglong2 c1 = cp[4*q+1];
                ulonglong2 c2 = cp[4*q+2];
                ulonglong2 c3 = cp[4*q+3];
                FMA2(a0, rf2[8*q+0], c0.x, a0); FMA2(a1, rf2[8*q+1], c0.y, a1);
                FMA2(a2, rf2[8*q+2], c1.x, a2); FMA2(a3, rf2[8*q+3], c1.y, a3);
                FMA2(a0, rf2[8*q+4], c2.x, a0); FMA2(a1, rf2[8*q+5], c2.y, a1);
                FMA2(a2, rf2[8*q+6], c3.x, a2); FMA2(a3, rf2[8*q+7], c3.y, a3);
            }
            ADD2(a0, a0, a1); ADD2(a2, a2, a3); ADD2(a0, a0, a2);
            float2 dp = unpack2(a0);
            float key = (sqr + csq[cur][m]) - 2.f * (dp.x + dp.y);

            if (key <= kthr) {       // cheap accept: stage to smem, no network
                unsigned int kb = __float_as_uint(key);
                kb ^= ((unsigned int)((int)kb >> 31)) | 0x80000000u;
                que[cnt][tid] = ((unsigned long long)kb << 32)
                              | (unsigned int)((t << 5) + m);
                cnt++;
            }
            if ((m & 3) == 3 && __any_sync(0xffffffffu, cnt >= QTRIG)) {
                #pragma unroll 1
                for (int i = 0; i < QDEPTH; i++) {
                    if (i < cnt) {
                        unsigned long long pk = que[i][tid];
                        if (pk < kq[15]) kq_insert(kq, pk);
                    }
                }
                cnt = 0;
                kthr = kq_thresh(kq[15]);
            }
        }
        __syncthreads();   // next buffer filled; current buffer reads done
    }
    #pragma unroll 1
    for (int i = 0; i < QDEPTH; i++) {
        if (i < cnt) {
            unsigned long long pk = que[i][tid];
            if (pk < kq[15]) kq_insert(kq, pk);
        }
    }

    int gbase = b * NNODE;
    int* outp = g_idx + (size_t)(gbase + row) * KNN;
    #pragma unroll
    for (int r = 0; r < KNN; r++) outp[r] = gbase + (int)(kq[r] & 0xffffffffu);
}

__global__ __launch_bounds__(256) void edge_stats_kernel() {
    __shared__ float ssum[256], ssq[256];
    int tid = threadIdx.x, g = tid >> 6, c = tid & 63;
    int node = blockIdx.x * 4 + g;
    const int* nb = g_idx + (size_t)node * KNN;
    float u = g_u[(size_t)node * HD + c];
    float s = 0.f, q = 0.f;
    #pragma unroll
    for (int k = 0; k < KNN; k++) {
        int j = nb[k];
        float p = u + g_v[(size_t)j * HD + c];
        s += p; q = fmaf(p, p, q);
    }
    ssum[tid] = s; ssq[tid] = q;
    __syncthreads();
    if (tid < 64) {
        s = ssum[c] + ssum[c+64] + ssum[c+128] + ssum[c+192];
        q = ssq[c]  + ssq[c+64]  + ssq[c+128]  + ssq[c+192];
        atomicAdd(&g_se[c], s); atomicAdd(&g_qe[c], q);
    }
}

__global__ __launch_bounds__(256) void edge_apply_kernel(
    const float* __restrict__ wc2, const float* __restrict__ bc2,
    const float* __restrict__ gc1, const float* __restrict__ bec1)
{
    __shared__ float wsh[64][64];
    __shared__ float esh[4][16][64];
    __shared__ float rsum[256], rsq[256];
    int tid = threadIdx.x, g = tid >> 6, c = tid & 63;

    const float4* w4 = (const float4*)wc2;
    #pragma unroll
    for (int i = 0; i < 4; i++) {
        int q = tid + i * 256;
        float4 v = w4[q];
        int e = q << 2;
        *(float4*)&wsh[e >> 6][e & 63] = v;
    }
    __syncthreads();
    unsigned long long wreg2[32];
    #pragma unroll
    for (int d = 0; d < 32; d++) wreg2[d] = pack2(wsh[2*d][c], wsh[2*d+1][c]);

    float invE = 1.f / (float)NEDGES;
    float m  = g_se[c] * invE;
    float var = g_qe[c] * invE - m * m;
    float sc = gc1[c] * rsqrtf(var + BNEPS);
    float sh = bec1[c] - m * sc;

    int node = blockIdx.x * 4 + g;
    const int* nb = g_idx + (size_t)node * KNN;
    float u = g_u[(size_t)node * HD + c];
    #pragma unroll
    for (int k = 0; k < KNN; k++) {
        int j = nb[k];
        float p = u + g_v[(size_t)j * HD + c];
        esh[g][k][c] = fmaxf(fmaf(p, sc, sh), 0.f);
    }
    __syncthreads();

    float acc = -FLT_MAX;
    float b2 = bc2[c];
    #pragma unroll 1
    for (int k = 0; k < KNN; k++) {
        unsigned long long a0 = 0ull, a1 = 0ull, a2 = 0ull, a3 = 0ull;
        const ulonglong2* ep = (const ulonglong2*)&esh[g][k][0];
        #pragma unroll
        for (int q = 0; q < 4; q++) {
            ulonglong2 e0 = ep[4*q+0];
            ulonglong2 e1 = ep[4*q+1];
            ulonglong2 e2 = ep[4*q+2];
            ulonglong2 e3 = ep[4*q+3];
            FMA2(a0, e0.x, wreg2[8*q+0], a0); FMA2(a1, e0.y, wreg2[8*q+1], a1);
            FMA2(a2, e1.x, wreg2[8*q+2], a2); FMA2(a3, e1.y, wreg2[8*q+3], a3);
            FMA2(a0, e2.x, wreg2[8*q+4], a0); FMA2(a1, e2.y, wreg2[8*q+5], a1);
            FMA2(a2, e3.x, wreg2[8*q+6], a2); FMA2(a3, e3.y, wreg2[8*q+7], a3);
        }
        ADD2(a0, a0, a1); ADD2(a2, a2, a3); ADD2(a0, a0, a2);
        float2 dp = unpack2(a0);
        float y = (dp.x + dp.y) + b2;
        acc = fmaxf(acc, y);
    }
    g_bufA[(size_t)node * HD + c] = acc;
    rsum[tid] = acc; rsq[tid] = acc * acc;
    __syncthreads();
    if (tid < 64) {
        float s = rsum[c] + rsum[c+64] + rsum[c+128] + rsum[c+192];
        float q = rsq[c]  + rsq[c+64]  + rsq[c+128]  + rsq[c+192];
        atomicAdd(&g_sp[c], s); atomicAdd(&g_qp[c], q);
    }
}

__global__ __launch_bounds__(256) void final_kernel(
    const float* __restrict__ gp, const float* __restrict__ bp, float* __restrict__ out)
{
    int t = blockIdx.x * 256 + threadIdx.x;
    int c4 = (t & 15) << 2;
    float invM = 1.f / (float)MNODES;
    float4 v = ((const float4*)g_bufA)[t];
    float* pv = &v.x;
    #pragma unroll
    for (int j = 0; j < 4; j++) {
        int cc = c4 + j;
        float m   = g_sp[cc] * invM;
        float var = g_qp[cc] * invM - m * m;
        float sc  = gp[cc] * rsqrtf(var + BNEPS);
        pv[j] = fmaxf(fmaf(pv[j], sc, bp[cc] - m * sc), 0.f);
    }
    ((float4*)out)[t] = v;
}

extern "C" void kernel_launch(void* const* d_in, const int* in_sizes, int n_in,
                              void* d_out, int out_size) {
    const float* x   = (const float*)d_in[0];
    const float* w1  = (const float*)d_in[2];  const float* b1  = (const float*)d_in[3];
    const float* g1  = (const float*)d_in[4];  const float* be1 = (const float*)d_in[5];
    const float* w2  = (const float*)d_in[6];  const float* b2  = (const float*)d_in[7];
    const float* g2  = (const float*)d_in[8];  const float* be2 = (const float*)d_in[9];
    const float* w3  = (const float*)d_in[10]; const float* b3  = (const float*)d_in[11];
    const float* g3  = (const float*)d_in[12]; const float* be3 = (const float*)d_in[13];
    const float* wc1 = (const float*)d_in[14]; const float* bc1 = (const float*)d_in[15];
    const float* gc1 = (const float*)d_in[16]; const float* bec1= (const float*)d_in[17];
    const float* wc2 = (const float*)d_in[18]; const float* bc2 = (const float*)d_in[19];
    const float* gp  = (const float*)d_in[20]; const float* bp  = (const float*)d_in[21];
    float* out = (float*)d_out;

    zero_stats_kernel<<<1, 64>>>();
    gemm_stage_kernel<<<MNODES/64, 256>>>(1, x, w1, b1, g1, be1);
    gemm_stage_kernel<<<MNODES/64, 256>>>(2, x, w2, b2, g1, be1);
    gemm_stage_kernel<<<MNODES/64, 256>>>(3, x, w3, b3, g2, be2);
    layer_uv_kernel<<<MNODES/64, 256>>>(wc1, bc1, g3, be3);
    knn_kernel<<<dim3(NNODE/128, BATCHG), 128>>>();
    edge_stats_kernel<<<MNODES/4, 256>>>();
    edge_apply_kernel<<<MNODES/4, 256>>>(wc2, bc2, gc1, bec1);
    final_kernel<<<MNODES*HD/4/256, 256>>>(gp, bp, out);
}

// round 17
// speedup vs baseline: 1.0162x; 1.0162x over previous
#include <cuda_runtime.h>
#include <float.h>

#define BATCHG 64
#define NNODE 1024
#define KNN 16
#define HD 64
#define MNODES (BATCHG*NNODE)
#define NEDGES (MNODES*KNN)
#define BNEPS 1e-5f

#define KQ_SENT 0xFF800000FFFFFFFFull
#define QDEPTH 16
#define QTRIG 12

#define FMA2(d, a, b, c) \
    asm("fma.rn.f32x2 %0, %1, %2, %3;" : "=l"(d) : "l"(a), "l"(b), "l"(c))
#define ADD2(d, a, b) \
    asm("add.rn.f32x2 %0, %1, %2;" : "=l"(d) : "l"(a), "l"(b))
__device__ __forceinline__ unsigned long long pack2(float lo, float hi) {
    unsigned long long r;
    asm("mov.b64 %0, {%1, %2};" : "=l"(r) : "r"(__float_as_uint(lo)), "r"(__float_as_uint(hi)));
    return r;
}
__device__ __forceinline__ float2 unpack2(unsigned long long v) {
    unsigned int lo, hi;
    asm("mov.b64 {%0, %1}, %2;" : "=r"(lo), "=r"(hi) : "l"(v));
    return make_float2(__uint_as_float(lo), __uint_as_float(hi));
}

__device__ float g_bufA[MNODES*HD];
__device__ float g_bufB[MNODES*HD];
__device__ float g_u[MNODES*HD];
__device__ float g_v[MNODES*HD];
__device__ float g_sq[MNODES];
__device__ int   g_idx[MNODES*KNN];
__device__ float g_s1[HD], g_q1[HD], g_s2[HD], g_q2[HD], g_s3[HD], g_q3[HD];
__device__ float g_se[HD], g_qe[HD], g_sp[HD], g_qp[HD];

__global__ void zero_stats_kernel() {
    int t = threadIdx.x;
    if (t < HD) {
        g_s1[t]=0.f; g_q1[t]=0.f; g_s2[t]=0.f; g_q2[t]=0.f; g_s3[t]=0.f; g_q3[t]=0.f;
        g_se[t]=0.f; g_qe[t]=0.f; g_sp[t]=0.f; g_qp[t]=0.f;
    }
}

// Linear(64,64)+bias; prev-stage BN+ReLU fused on input; output stats. (R9 exact)
__global__ __launch_bounds__(256) void gemm_stage_kernel(
    int stage, const float* __restrict__ xin,
    const float* __restrict__ w, const float* __restrict__ bias,
    const float* __restrict__ gam, const float* __restrict__ bet)
{
    __shared__ float xs[64][64];
    __shared__ float ws[64][64];
    __shared__ float scs[64], shs[64];
    __shared__ float rs[64], rq[64];

    const float* in; float* out; float* osum; float* osq;
    const float* psum = 0; const float* psq = 0;
    if (stage == 1)      { in = xin;    out = g_bufA; osum = g_s1; osq = g_q1; }
    else if (stage == 2) { in = g_bufA; out = g_bufB; osum = g_s2; osq = g_q2; psum = g_s1; psq = g_q1; }
    else                 { in = g_bufB; out = g_bufA; osum = g_s3; osq = g_q3; psum = g_s2; psq = g_q2; }

    int tid = threadIdx.x;
    int rowBase = blockIdx.x * 64;

    if (tid < 64) {
        rs[tid] = 0.f; rq[tid] = 0.f;
        if (stage > 1) {
            float invM = 1.f / (float)MNODES;
            float m   = psum[tid] * invM;
            float var = psq[tid] * invM - m * m;
            float s   = gam[tid] * rsqrtf(var + BNEPS);
            scs[tid] = s; shs[tid] = bet[tid] - m * s;
        }
    }
    const float4* w4 = (const float4*)w;
    #pragma unroll
    for (int i = 0; i < 4; i++) {
        int q = tid + i * 256;
        float4 v = w4[q];
        int e = q << 2;
        *(float4*)&ws[e >> 6][e & 63] = v;
    }
    __syncthreads();
    const float4* in4 = (const float4*)(in + (size_t)rowBase * HD);
    #pragma unroll
    for (int i = 0; i < 4; i++) {
        int q = tid + i * 256;
        float4 v = in4[q];
        int e = q << 2; int c = e & 63;
        if (stage > 1) {
            v.x = fmaxf(fmaf(v.x, scs[c+0], shs[c+0]), 0.f);
            v.y = fmaxf(fmaf(v.y, scs[c+1], shs[c+1]), 0.f);
            v.z = fmaxf(fmaf(v.z, scs[c+2], shs[c+2]), 0.f);
            v.w = fmaxf(fmaf(v.w, scs[c+3], shs[c+3]), 0.f);
        }
        *(float4*)&xs[e >> 6][c] = v;
    }
    __syncthreads();

    int r0 = (tid >> 4) << 2, c0 = (tid & 15) << 2;
    float acc[4][4];
    #pragma unroll
    for (int i = 0; i < 4; i++)
        #pragma unroll
        for (int j = 0; j < 4; j++) acc[i][j] = 0.f;

    #pragma unroll
    for (int d = 0; d < 64; d++) {
        float x0 = xs[r0+0][d], x1 = xs[r0+1][d], x2 = xs[r0+2][d], x3 = xs[r0+3][d];
        float w0 = ws[d][c0+0], w1 = ws[d][c0+1], w2 = ws[d][c0+2], w3 = ws[d][c0+3];
        acc[0][0]=fmaf(x0,w0,acc[0][0]); acc[0][1]=fmaf(x0,w1,acc[0][1]); acc[0][2]=fmaf(x0,w2,acc[0][2]); acc[0][3]=fmaf(x0,w3,acc[0][3]);
        acc[1][0]=fmaf(x1,w0,acc[1][0]); acc[1][1]=fmaf(x1,w1,acc[1][1]); acc[1][2]=fmaf(x1,w2,acc[1][2]); acc[1][3]=fmaf(x1,w3,acc[1][3]);
        acc[2][0]=fmaf(x2,w0,acc[2][0]); acc[2][1]=fmaf(x2,w1,acc[2][1]); acc[2][2]=fmaf(x2,w2,acc[2][2]); acc[2][3]=fmaf(x2,w3,acc[2][3]);
        acc[3][0]=fmaf(x3,w0,acc[3][0]); acc[3][1]=fmaf(x3,w1,acc[3][1]); acc[3][2]=fmaf(x3,w2,acc[3][2]); acc[3][3]=fmaf(x3,w3,acc[3][3]);
    }
    float b0 = bias[c0+0], b1 = bias[c0+1], b2 = bias[c0+2], b3 = bias[c0+3];
    float lsum[4] = {0,0,0,0}, lsq[4] = {0,0,0,0};
    #pragma unroll
    for (int i = 0; i < 4; i++) {
        float4 o;
        o.x = acc[i][0] + b0; o.y = acc[i][1] + b1; o.z = acc[i][2] + b2; o.w = acc[i][3] + b3;
        *(float4*)(out + (size_t)(rowBase + r0 + i) * HD + c0) = o;
        lsum[0]+=o.x; lsq[0]=fmaf(o.x,o.x,lsq[0]);
        lsum[1]+=o.y; lsq[1]=fmaf(o.y,o.y,lsq[1]);
        lsum[2]+=o.z; lsq[2]=fmaf(o.z,o.z,lsq[2]);
        lsum[3]+=o.w; lsq[3]=fmaf(o.w,o.w,lsq[3]);
    }
    #pragma unroll
    for (int j = 0; j < 4; j++) { atomicAdd(&rs[c0+j], lsum[j]); atomicAdd(&rq[c0+j], lsq[j]); }
    __syncthreads();
    if (tid < 64) { atomicAdd(&osum[tid], rs[tid]); atomicAdd(&osq[tid], rq[tid]); }
}

// h = bn3relu(y3) -> g_bufB; u,v; g_sq row norms. (R9 exact)
__global__ __launch_bounds__(256) void layer_uv_kernel(
    const float* __restrict__ wc1, const float* __restrict__ bc1,
    const float* __restrict__ g3p, const float* __restrict__ be3p)
{
    __shared__ float xs[64][64];
    __shared__ float wa[64][64];
    __shared__ float wb[64][64];
    int tid = threadIdx.x;
    int rowBase = blockIdx.x * 64;

    const float4* w4 = (const float4*)wc1;
    #pragma unroll
    for (int i = 0; i < 4; i++) {
        int q = tid + i * 256;
        float4 va = w4[q];
        float4 vb = w4[q + 1024];
        int e = q << 2;
        float4 d4 = make_float4(va.x - vb.x, va.y - vb.y, va.z - vb.z, va.w - vb.w);
        *(float4*)&wa[e >> 6][e & 63] = d4;
        *(float4*)&wb[e >> 6][e & 63] = vb;
    }
    float invM = 1.f / (float)MNODES;
    const float4* in4 = (const float4*)(g_bufA + (size_t)rowBase * HD);
    float4* h4 = (float4*)(g_bufB + (size_t)rowBase * HD);
    float psq[4];
    #pragma unroll
    for (int i = 0; i < 4; i++) {
        int q = tid + i * 256;
        float4 v = in4[q];
        int e = q << 2; int c = e & 63;
        float* pv = &v.x;
        #pragma unroll
        for (int j = 0; j < 4; j++) {
            int cc = c + j;
            float m   = g_s3[cc] * invM;
            float var = g_q3[cc] * invM - m * m;
            float sc  = g3p[cc] * rsqrtf(var + BNEPS);
            pv[j] = fmaxf(fmaf(pv[j], sc, be3p[cc] - m * sc), 0.f);
        }
        *(float4*)&xs[e >> 6][c] = v;
        h4[q] = v;
        psq[i] = v.x*v.x + v.y*v.y + v.z*v.z + v.w*v.w;
    }
    #pragma unroll
    for (int i = 0; i < 4; i++) {
        #pragma unroll
        for (int off = 8; off; off >>= 1)
            psq[i] += __shfl_xor_sync(0xffffffffu, psq[i], off, 16);
    }
    if ((tid & 15) == 0) {
        int r = tid >> 4;
        #pragma unroll
        for (int i = 0; i < 4; i++)
            g_sq[rowBase + r + 16*i] = psq[i];
    }
    __syncthreads();

    int r0 = (tid >> 4) << 2, c0 = (tid & 15) << 2;
    float au[4][4], av[4][4];
    #pragma unroll
    for (int i = 0; i < 4; i++)
        #pragma unroll
        for (int j = 0; j < 4; j++) { au[i][j] = 0.f; av[i][j] = 0.f; }

    #pragma unroll
    for (int d = 0; d < 64; d++) {
        float x0 = xs[r0+0][d], x1 = xs[r0+1][d], x2 = xs[r0+2][d], x3 = xs[r0+3][d];
        float a0 = wa[d][c0+0], a1 = wa[d][c0+1], a2 = wa[d][c0+2], a3 = wa[d][c0+3];
        float p0 = wb[d][c0+0], p1 = wb[d][c0+1], p2 = wb[d][c0+2], p3 = wb[d][c0+3];
        au[0][0]=fmaf(x0,a0,au[0][0]); au[0][1]=fmaf(x0,a1,au[0][1]); au[0][2]=fmaf(x0,a2,au[0][2]); au[0][3]=fmaf(x0,a3,au[0][3]);
        au[1][0]=fmaf(x1,a0,au[1][0]); au[1][1]=fmaf(x1,a1,au[1][1]); au[1][2]=fmaf(x1,a2,au[1][2]); au[1][3]=fmaf(x1,a3,au[1][3]);
        au[2][0]=fmaf(x2,a0,au[2][0]); au[2][1]=fmaf(x2,a1,au[2][1]); au[2][2]=fmaf(x2,a2,au[2][2]); au[2][3]=fmaf(x2,a3,au[2][3]);
        au[3][0]=fmaf(x3,a0,au[3][0]); au[3][1]=fmaf(x3,a1,au[3][1]); au[3][2]=fmaf(x3,a2,au[3][2]); au[3][3]=fmaf(x3,a3,au[3][3]);
        av[0][0]=fmaf(x0,p0,av[0][0]); av[0][1]=fmaf(x0,p1,av[0][1]); av[0][2]=fmaf(x0,p2,av[0][2]); av[0][3]=fmaf(x0,p3,av[0][3]);
        av[1][0]=fmaf(x1,p0,av[1][0]); av[1][1]=fmaf(x1,p1,av[1][1]); av[1][2]=fmaf(x1,p2,av[1][2]); av[1][3]=fmaf(x1,p3,av[1][3]);
        av[2][0]=fmaf(x2,p0,av[2][0]); av[2][1]=fmaf(x2,p1,av[2][1]); av[2][2]=fmaf(x2,p2,av[2][2]); av[2][3]=fmaf(x2,p3,av[2][3]);
        av[3][0]=fmaf(x3,p0,av[3][0]); av[3][1]=fmaf(x3,p1,av[3][1]); av[3][2]=fmaf(x3,p2,av[3][2]); av[3][3]=fmaf(x3,p3,av[3][3]);
    }
    float bA = bc1[c0+0], bB = bc1[c0+1], bC = bc1[c0+2], bD = bc1[c0+3];
    #pragma unroll
    for (int i = 0; i < 4; i++) {
        float4 uo = make_float4(au[i][0]+bA, au[i][1]+bB, au[i][2]+bC, au[i][3]+bD);
        float4 vo = make_float4(av[i][0], av[i][1], av[i][2], av[i][3]);
        *(float4*)(g_u + (size_t)(rowBase + r0 + i) * HD + c0) = uo;
        *(float4*)(g_v + (size_t)(rowBase + r0 + i) * HD + c0) = vo;
    }
}

__device__ __forceinline__ void kq_insert(unsigned long long (&kq)[16], unsigned long long e) {
    kq[15] = e;
    #pragma unroll
    for (int p = 15; p > 0; p--) {
        bool sw = kq[p] < kq[p-1];
        unsigned long long lo = sw ? kq[p] : kq[p-1];
        unsigned long long hi = sw ? kq[p-1] : kq[p];
        kq[p-1] = lo; kq[p] = hi;
    }
}
__device__ __forceinline__ float kq_thresh(unsigned long long kq15) {
    unsigned int u = (unsigned int)(kq15 >> 32);
    u = (u & 0x80000000u) ? (u ^ 0x80000000u) : ~u;
    return __uint_as_float(u);
}

// kNN: R15 exact (single-buffer tiles, 128 thr, occ 4) with the warp ballot
// batched to every 4th candidate (QDEPTH 16, trigger >= 12; provably no
// queue overflow: cnt < 12 at any check -> <= 15 before the next).
__global__ __launch_bounds__(128, 4) void knn_kernel() {
    __shared__ float cand[32][68];
    __shared__ float csq[32];
    __shared__ unsigned long long que[QDEPTH][128];
    int b = blockIdx.y;
    int tid = threadIdx.x;
    int row = blockIdx.x * 128 + tid;
    const float* hb = g_bufB + (size_t)b * NNODE * HD;

    unsigned long long rf2[32];
    {
        const ulonglong2* rp = (const ulonglong2*)(hb + (size_t)row * HD);
        #pragma unroll
        for (int i = 0; i < 16; i++) {
            ulonglong2 t = rp[i];
            rf2[2*i] = t.x; rf2[2*i+1] = t.y;
        }
    }
    float sqr = g_sq[b * NNODE + row];

    unsigned long long kq[16];
    #pragma unroll
    for (int p = 0; p < 16; p++) kq[p] = KQ_SENT;
    float kthr = __uint_as_float(0x7F800000u);   // +inf
    int cnt = 0;

    #pragma unroll 1
    for (int t = 0; t < 32; t++) {
        __syncthreads();
        #pragma unroll
        for (int i = 0; i < 4; i++) {
            int fi = tid + i * 128;              // float4 index in 32x16 tile
            int r = fi >> 4, c4 = fi & 15;
            float4 v = *(const float4*)(hb + (size_t)((t << 5) + r) * HD + (c4 << 2));
            *(float4*)&cand[r][c4 << 2] = v;
        }
        if (tid < 32) csq[tid] = g_sq[b * NNODE + (t << 5) + tid];
        __syncthreads();

        #pragma unroll 1
        for (int m = 0; m < 32; m++) {
            unsigned long long a0 = 0ull, a1 = 0ull, a2 = 0ull, a3 = 0ull;
            const ulonglong2* cp = (const ulonglong2*)&cand[m][0];
            #pragma unroll
            for (int q = 0; q < 4; q++) {
                ulonglong2 c0 = cp[4*q+0];
                ulonglong2 c1 = cp[4*q+1];
                ulonglong2 c2 = cp[4*q+2];
                ulonglong2 c3 = cp[4*q+3];
                FMA2(a0, rf2[8*q+0], c0.x, a0); FMA2(a1, rf2[8*q+1], c0.y, a1);
                FMA2(a2, rf2[8*q+2], c1.x, a2); FMA2(a3, rf2[8*q+3], c1.y, a3);
                FMA2(a0, rf2[8*q+4], c2.x, a0); FMA2(a1, rf2[8*q+5], c2.y, a1);
                FMA2(a2, rf2[8*q+6], c3.x, a2); FMA2(a3, rf2[8*q+7], c3.y, a3);
            }
            ADD2(a0, a0, a1); ADD2(a2, a2, a3); ADD2(a0, a0, a2);
            float2 dp = unpack2(a0);
            float key = (sqr + csq[m]) - 2.f * (dp.x + dp.y);

            if (key <= kthr) {       // cheap accept: stage to smem, no network
                unsigned int kb = __float_as_uint(key);
                kb ^= ((unsigned int)((int)kb >> 31)) | 0x80000000u;
                que[cnt][tid] = ((unsigned long long)kb << 32)
                              | (unsigned int)((t << 5) + m);
                cnt++;
            }
            if ((m & 3) == 3 && __any_sync(0xffffffffu, cnt >= QTRIG)) {
                #pragma unroll 1
                for (int i = 0; i < QDEPTH; i++) {
                    if (i < cnt) {
                        unsigned long long pk = que[i][tid];
                        if (pk < kq[15]) kq_insert(kq, pk);
                    }
                }
                cnt = 0;
                kthr = kq_thresh(kq[15]);
            }
        }
    }
    #pragma unroll 1
    for (int i = 0; i < QDEPTH; i++) {
        if (i < cnt) {
            unsigned long long pk = que[i][tid];
            if (pk < kq[15]) kq_insert(kq, pk);
        }
    }

    int gbase = b * NNODE;
    int* outp = g_idx + (size_t)(gbase + row) * KNN;
    #pragma unroll
    for (int r = 0; r < KNN; r++) outp[r] = gbase + (int)(kq[r] & 0xffffffffu);
}

__global__ __launch_bounds__(256) void edge_stats_kernel() {
    __shared__ float ssum[256], ssq[256];
    int tid = threadIdx.x, g = tid >> 6, c = tid & 63;
    int node = blockIdx.x * 4 + g;
    const int* nb = g_idx + (size_t)node * KNN;
    float u = g_u[(size_t)node * HD + c];
    float s = 0.f, q = 0.f;
    #pragma unroll
    for (int k = 0; k < KNN; k++) {
        int j = nb[k];
        float p = u + g_v[(size_t)j * HD + c];
        s += p; q = fmaf(p, p, q);
    }
    ssum[tid] = s; ssq[tid] = q;
    __syncthreads();
    if (tid < 64) {
        s = ssum[c] + ssum[c+64] + ssum[c+128] + ssum[c+192];
        q = ssq[c]  + ssq[c+64]  + ssq[c+128]  + ssq[c+192];
        atomicAdd(&g_se[c], s); atomicAdd(&g_qe[c], q);
    }
}

__global__ __launch_bounds__(256) void edge_apply_kernel(
    const float* __restrict__ wc2, const float* __restrict__ bc2,
    const float* __restrict__ gc1, const float* __restrict__ bec1)
{
    __shared__ float wsh[64][64];
    __shared__ float esh[4][16][64];
    __shared__ float rsum[256], rsq[256];
    int tid = threadIdx.x, g = tid >> 6, c = tid & 63;

    const float4* w4 = (const float4*)wc2;
    #pragma unroll
    for (int i = 0; i < 4; i++) {
        int q = tid + i * 256;
        float4 v = w4[q];
        int e = q << 2;
        *(float4*)&wsh[e >> 6][e & 63] = v;
    }
    __syncthreads();
    unsigned long long wreg2[32];
    #pragma unroll
    for (int d = 0; d < 32; d++) wreg2[d] = pack2(wsh[2*d][c], wsh[2*d+1][c]);

    float invE = 1.f / (float)NEDGES;
    float m  = g_se[c] * invE;
    float var = g_qe[c] * invE - m * m;
    float sc = gc1[c] * rsqrtf(var + BNEPS);
    float sh = bec1[c] - m * sc;

    int node = blockIdx.x * 4 + g;
    const int* nb = g_idx + (size_t)node * KNN;
    float u = g_u[(size_t)node * HD + c];
    #pragma unroll
    for (int k = 0; k < KNN; k++) {
        int j = nb[k];
        float p = u + g_v[(size_t)j * HD + c];
        esh[g][k][c] = fmaxf(fmaf(p, sc, sh), 0.f);
    }
    __syncthreads();

    float acc = -FLT_MAX;
    float b2 = bc2[c];
    #pragma unroll 1
    for (int k = 0; k < KNN; k++) {
        unsigned long long a0 = 0ull, a1 = 0ull, a2 = 0ull, a3 = 0ull;
        const ulonglong2* ep = (const ulonglong2*)&esh[g][k][0];
        #pragma unroll
        for (int q = 0; q < 4; q++) {
            ulonglong2 e0 = ep[4*q+0];
            ulonglong2 e1 = ep[4*q+1];
            ulonglong2 e2 = ep[4*q+2];
            ulonglong2 e3 = ep[4*q+3];
            FMA2(a0, e0.x, wreg2[8*q+0], a0); FMA2(a1, e0.y, wreg2[8*q+1], a1);
            FMA2(a2, e1.x, wreg2[8*q+2], a2); FMA2(a3, e1.y, wreg2[8*q+3], a3);
            FMA2(a0, e2.x, wreg2[8*q+4], a0); FMA2(a1, e2.y, wreg2[8*q+5], a1);
            FMA2(a2, e3.x, wreg2[8*q+6], a2); FMA2(a3, e3.y, wreg2[8*q+7], a3);
        }
        ADD2(a0, a0, a1); ADD2(a2, a2, a3); ADD2(a0, a0, a2);
        float2 dp = unpack2(a0);
        float y = (dp.x + dp.y) + b2;
        acc = fmaxf(acc, y);
    }
    g_bufA[(size_t)node * HD + c] = acc;
    rsum[tid] = acc; rsq[tid] = acc * acc;
    __syncthreads();
    if (tid < 64) {
        float s = rsum[c] + rsum[c+64] + rsum[c+128] + rsum[c+192];
        float q = rsq[c]  + rsq[c+64]  + rsq[c+128]  + rsq[c+192];
        atomicAdd(&g_sp[c], s); atomicAdd(&g_qp[c], q);
    }
}

__global__ __launch_bounds__(256) void final_kernel(
    const float* __restrict__ gp, const float* __restrict__ bp, float* __restrict__ out)
{
    int t = blockIdx.x * 256 + threadIdx.x;
    int c4 = (t & 15) << 2;
    float invM = 1.f / (float)MNODES;
    float4 v = ((const float4*)g_bufA)[t];
    float* pv = &v.x;
    #pragma unroll
    for (int j = 0; j < 4; j++) {
        int cc = c4 + j;
        float m   = g_sp[cc] * invM;
        float var = g_qp[cc] * invM - m * m;
        float sc  = gp[cc] * rsqrtf(var + BNEPS);
        pv[j] = fmaxf(fmaf(pv[j], sc, bp[cc] - m * sc), 0.f);
    }
    ((float4*)out)[t] = v;
}

extern "C" void kernel_launch(void* const* d_in, const int* in_sizes, int n_in,
                              void* d_out, int out_size) {
    const float* x   = (const float*)d_in[0];
    const float* w1  = (const float*)d_in[2];  const float* b1  = (const float*)d_in[3];
    const float* g1  = (const float*)d_in[4];  const float* be1 = (const float*)d_in[5];
    const float* w2  = (const float*)d_in[6];  const float* b2  = (const float*)d_in[7];
    const float* g2  = (const float*)d_in[8];  const float* be2 = (const float*)d_in[9];
    const float* w3  = (const float*)d_in[10]; const float* b3  = (const float*)d_in[11];
    const float* g3  = (const float*)d_in[12]; const float* be3 = (const float*)d_in[13];
    const float* wc1 = (const float*)d_in[14]; const float* bc1 = (const float*)d_in[15];
    const float* gc1 = (const float*)d_in[16]; const float* bec1= (const float*)d_in[17];
    const float* wc2 = (const float*)d_in[18]; const float* bc2 = (const float*)d_in[19];
    const float* gp  = (const float*)d_in[20]; const float* bp  = (const float*)d_in[21];
    float* out = (float*)d_out;

    zero_stats_kernel<<<1, 64>>>();
    gemm_stage_kernel<<<MNODES/64, 256>>>(1, x, w1, b1, g1, be1);
    gemm_stage_kernel<<<MNODES/64, 256>>>(2, x, w2, b2, g1, be1);
    gemm_stage_kernel<<<MNODES/64, 256>>>(3, x, w3, b3, g2, be2);
    layer_uv_kernel<<<MNODES/64, 256>>>(wc1, bc1, g3, be3);
    knn_kernel<<<dim3(NNODE/128, BATCHG), 128>>>();
    edge_stats_kernel<<<MNODES/4, 256>>>();
    edge_apply_kernel<<<MNODES/4, 256>>>(wc2, bc2, gc1, bec1);
    final_kernel<<<MNODES*HD/4/256, 256>>>(gp, bp, out);
}